// round 12
// baseline (speedup 1.0000x reference)
#include <cuda_runtime.h>
#include <cuda_fp16.h>
#include <math.h>
#include <stdint.h>

#define B_DIM 32
#define T_DIM 2048
#define H_DIM 1024
#define OCG   4                                 // oc groups (CTAs per row-block)

// ---------------------------------------------------------------------------
// Scratch (allocation-free rule: __device__ globals)
// ---------------------------------------------------------------------------
__device__ float  g_qproj[B_DIM * H_DIM];
__device__ float  g_score_part[OCG * B_DIM * T_DIM];
__device__ float  g_ctx_part[B_DIM * 8 * H_DIM];
__device__ __half g_vals_h[(size_t)B_DIM * T_DIM * H_DIM];   // 128 MB
__device__ __half g_wv_h[H_DIM * H_DIM];

// ---------------------------------------------------------------------------
// PTX helpers (sm_80-compatible; tcgen05 is NOT available at compute_103)
// ---------------------------------------------------------------------------
__device__ __forceinline__ uint32_t smem_u32(const void* p) {
    uint32_t a;
    asm("{ .reg .u64 t; cvta.to.shared.u64 t, %1; cvt.u32.u64 %0, t; }" : "=r"(a) : "l"(p));
    return a;
}
__device__ __forceinline__ void cp_async16(uint32_t dst, const void* src) {
    asm volatile("cp.async.cg.shared.global [%0], [%1], 16;" :: "r"(dst), "l"(src));
}
__device__ __forceinline__ void cp_commit() {
    asm volatile("cp.async.commit_group;" ::: "memory");
}
template <int N>
__device__ __forceinline__ void cp_wait() {
    asm volatile("cp.async.wait_group %0;" :: "n"(N) : "memory");
}
__device__ __forceinline__ void ldsm_x4(uint32_t r[4], uint32_t addr) {
    asm volatile("ldmatrix.sync.aligned.m8n8.x4.shared.b16 {%0,%1,%2,%3}, [%4];"
                 : "=r"(r[0]), "=r"(r[1]), "=r"(r[2]), "=r"(r[3]) : "r"(addr));
}
__device__ __forceinline__ void mma_f16(float c[4], const uint32_t a[4], const uint32_t b[2]) {
    asm volatile(
        "mma.sync.aligned.m16n8k16.row.col.f32.f16.f16.f32 "
        "{%0,%1,%2,%3}, {%4,%5,%6,%7}, {%8,%9}, {%0,%1,%2,%3};"
        : "+f"(c[0]), "+f"(c[1]), "+f"(c[2]), "+f"(c[3])
        : "r"(a[0]), "r"(a[1]), "r"(a[2]), "r"(a[3]), "r"(b[0]), "r"(b[1]));
}
__device__ __forceinline__ float fast_tanh(float x) {
    float e = __expf(2.0f * x);
    return 1.0f - 2.0f / (e + 1.0f);
}

// ---------------------------------------------------------------------------
// Kernel 0: fp32 -> fp16 conversion (grid-stride over float4)
// ---------------------------------------------------------------------------
__global__ void convert_kernel(const float* __restrict__ src, __half* __restrict__ dst,
                               int n4) {
    int i = blockIdx.x * blockDim.x + threadIdx.x;
    const int stride = gridDim.x * blockDim.x;
    for (; i < n4; i += stride) {
        float4 v = ((const float4*)src)[i];
        __half2 h0 = __floats2half2_rn(v.x, v.y);
        __half2 h1 = __floats2half2_rn(v.z, v.w);
        ((__half2*)dst)[2 * i + 0] = h0;
        ((__half2*)dst)[2 * i + 1] = h1;
    }
}

// ---------------------------------------------------------------------------
// Kernel 1: q_proj, grid (8 oc, 32 b): warp per output, 16 outputs per warp.
// ---------------------------------------------------------------------------
__global__ void qproj_kernel(const float* __restrict__ query,
                             const float* __restrict__ Wq,
                             const float* __restrict__ bq) {
    __shared__ float q_s[H_DIM];
    const int b = blockIdx.y;
    const int ob = blockIdx.x * 128;
    const int tid = threadIdx.x;
    for (int i = tid; i < H_DIM; i += 256) q_s[i] = query[b * H_DIM + i];
    __syncthreads();
    const int warp = tid >> 5, lane = tid & 31;
    for (int oi = 0; oi < 16; ++oi) {
        const int o = ob + warp * 16 + oi;
        const float* wrow = Wq + (size_t)o * H_DIM;
        float s = 0.f;
        #pragma unroll 8
        for (int h = lane; h < H_DIM; h += 32) s += q_s[h] * wrow[h];
        #pragma unroll
        for (int m = 16; m > 0; m >>= 1) s += __shfl_xor_sync(0xffffffffu, s, m);
        if (lane == 0) g_qproj[b * H_DIM + o] = s + bq[o];
    }
}

// ---------------------------------------------------------------------------
// Kernel 2: fused score GEMM, fp16 m16n8k16 mma.sync + ldmatrix.
// 32x32 warp tiles (C=32 regs) -> 3 CTAs/SM = 24 warps/SM for latency hiding.
// Block tile 128(M) x 64(N); 16 o-chunks of 64, OC_PER=4 per CTA, OCG=4.
// BK=32, STAGES=4 cp.async pipeline. 256 threads = 8 warps (4m x 2n).
// ---------------------------------------------------------------------------
#define BK       32
#define STAGES   4
#define NKT      (H_DIM / BK)                  // 32
#define LDPH     40                            // padded row stride (halves), 80B
#define ST_A     (128 * LDPH)                  // 5120 halves per A stage
#define ST_B     (64 * LDPH)                   // 2560 halves per B stage
#define OFF_AH   0
#define OFF_BH   (STAGES * ST_A)
#define HALVES   (STAGES * (ST_A + ST_B))      // 30720 halves
#define OFF_QB   (HALVES / 2)                  // float index
#define OFF_VW   (OFF_QB + 64)
#define OFF_SC   (OFF_VW + 64)
#define SMEM_FLT (OFF_SC + 128)
#define SMEM_BYTES (SMEM_FLT * 4)              // 62464 B
#define OC_PER   4                             // 64-wide o-chunks per CTA

__global__ void __launch_bounds__(256, 3) score_kernel(
    const float* __restrict__ bv,
    const float* __restrict__ Vw) {

    extern __shared__ __align__(16) float smem[];
    __half* As = (__half*)smem + OFF_AH;      // [STAGES][128][40]
    __half* Bs = (__half*)smem + OFF_BH;      // [STAGES][64][40]
    float* qb_s = smem + OFF_QB;
    float* vw_s = smem + OFF_VW;
    float* score_s = smem + OFF_SC;

    const int tid = threadIdx.x;
    const int wid = tid >> 5, lane = tid & 31;
    const int warp_m = wid >> 1, warp_n = wid & 1;   // 4 x 2
    const int gid = lane >> 2, tig = lane & 3;
    const int l8 = lane & 7, sel = lane >> 3;

    // Per-warp K-step phase rotation (2 k16 steps per kt)
    const int ks0 = wid & 1;

    const int r0 = blockIdx.x * 128;
    const int grp = blockIdx.y;                  // oc group
    const int b  = r0 / T_DIM;
    const float* qp = g_qproj + b * H_DIM;

    if (tid < 128) score_s[tid] = 0.f;

    // Loader constants: A = 128 rows x 4 chunks (2 iters), B = 64 rows x 4 (1 iter)
    const int ld_row = tid >> 2;                 // 0..63
    const int ld_ch  = tid & 3;
    const uint32_t ld_soff = (uint32_t)(ld_row * LDPH + ld_ch * 8) * 2;  // bytes
    const uint32_t a_sbase = smem_u32(As) + ld_soff;
    const uint32_t b_sbase = smem_u32(Bs) + ld_soff;
    const __half* a_gbase = g_vals_h + (size_t)(r0 + ld_row) * H_DIM + ld_ch * 8;
    const size_t  a_half_step = (size_t)64 * H_DIM;   // rows 64..127

    // ldmatrix lane addressing (halves)
    const int a_row = warp_m * 32 + ((sel & 1) ? 8 : 0) + l8;
    const int a_kof = (sel & 2) ? 8 : 0;
    const int b_row = warp_n * 32 + ((sel & 2) ? 8 : 0) + l8;
    const int b_kof = (sel & 1) ? 8 : 0;
    const uint32_t a_lbase = smem_u32(As + a_row * LDPH + a_kof);
    const uint32_t b_lbase = smem_u32(Bs + b_row * LDPH + b_kof);
    const uint32_t stg_a = ST_A * 2;             // stage strides in bytes
    const uint32_t stg_b = ST_B * 2;

    float sacc[4] = {0.f, 0.f, 0.f, 0.f};

    for (int oc = grp * OC_PER; oc < grp * OC_PER + OC_PER; ++oc) {
        const int ob = oc * 64;
        const __half* b_gbase = g_wv_h + (size_t)(ob + ld_row) * H_DIM + ld_ch * 8;
        __syncthreads();                 // prev pass fully done (epilogue + slots)
        if (tid < 64) {
            qb_s[tid] = qp[ob + tid] + bv[ob + tid];
            vw_s[tid] = Vw[ob + tid];
        }

        float c[2][4][4];
        #pragma unroll
        for (int mt = 0; mt < 2; ++mt)
            #pragma unroll
            for (int nt = 0; nt < 4; ++nt)
                #pragma unroll
                for (int i = 0; i < 4; ++i) c[mt][nt][i] = 0.f;

        // prologue: fill stages 0..2
        #pragma unroll
        for (int s = 0; s < STAGES - 1; ++s) {
            cp_async16(a_sbase + s * stg_a, a_gbase + s * BK);
            cp_async16(a_sbase + s * stg_a + 64 * LDPH * 2,
                       a_gbase + s * BK + a_half_step);
            cp_async16(b_sbase + s * stg_b, b_gbase + s * BK);
            cp_commit();
        }

        int cur = 0, nxt = STAGES - 1;
        for (int kt = 0; kt < NKT; ++kt) {
            cp_wait<STAGES - 2>();       // stage `cur` complete
            __syncthreads();             // slot `nxt` free (consumed at kt-1)

            const int nk = kt + STAGES - 1;
            if (nk < NKT) {
                cp_async16(a_sbase + nxt * stg_a, a_gbase + nk * BK);
                cp_async16(a_sbase + nxt * stg_a + 64 * LDPH * 2,
                           a_gbase + nk * BK + a_half_step);
                cp_async16(b_sbase + nxt * stg_b, b_gbase + nk * BK);
            }
            cp_commit();

            const uint32_t a_base = a_lbase + cur * stg_a;
            const uint32_t b_base = b_lbase + cur * stg_b;

            #pragma unroll
            for (int kss = 0; kss < 2; ++kss) {              // two k16 steps
                const int ks = (kss + ks0) & 1;
                const uint32_t koff = (uint32_t)ks * 32;     // 16 halves = 32B
                uint32_t af[2][4], bf[4][2];
                #pragma unroll
                for (int mt = 0; mt < 2; ++mt)
                    ldsm_x4(af[mt], a_base + mt * (16 * LDPH * 2) + koff);
                #pragma unroll
                for (int np = 0; np < 2; ++np) {
                    uint32_t r[4];
                    ldsm_x4(r, b_base + np * (16 * LDPH * 2) + koff);
                    bf[np * 2 + 0][0] = r[0];
                    bf[np * 2 + 0][1] = r[1];
                    bf[np * 2 + 1][0] = r[2];
                    bf[np * 2 + 1][1] = r[3];
                }
                #pragma unroll
                for (int mt = 0; mt < 2; ++mt)
                    #pragma unroll
                    for (int nt = 0; nt < 4; ++nt)
                        mma_f16(c[mt][nt], af[mt], bf[nt]);
            }

            cur = (cur == STAGES - 1) ? 0 : cur + 1;
            nxt = (nxt == STAGES - 1) ? 0 : nxt + 1;
        }

        // Epilogue: tanh + Vw contraction into per-lane row partials
        #pragma unroll
        for (int nt = 0; nt < 4; ++nt) {
            const int col0 = warp_n * 32 + nt * 8 + 2 * tig;
            const float vw0 = vw_s[col0],     qb0 = qb_s[col0];
            const float vw1 = vw_s[col0 + 1], qb1 = qb_s[col0 + 1];
            #pragma unroll
            for (int mt = 0; mt < 2; ++mt) {
                sacc[mt * 2 + 0] += vw0 * fast_tanh(c[mt][nt][0] + qb0)
                                  + vw1 * fast_tanh(c[mt][nt][1] + qb1);
                sacc[mt * 2 + 1] += vw0 * fast_tanh(c[mt][nt][2] + qb0)
                                  + vw1 * fast_tanh(c[mt][nt][3] + qb1);
            }
        }
    }

    #pragma unroll
    for (int i = 0; i < 4; ++i) {
        sacc[i] += __shfl_xor_sync(0xffffffffu, sacc[i], 1);
        sacc[i] += __shfl_xor_sync(0xffffffffu, sacc[i], 2);
    }
    if (tig == 0) {
        #pragma unroll
        for (int i = 0; i < 4; ++i) {
            const int row = warp_m * 32 + (i >> 1) * 16 + gid + (i & 1) * 8;
            atomicAdd(&score_s[row], sacc[i]);
        }
    }
    __syncthreads();
    if (tid < 128) g_score_part[grp * (B_DIM * T_DIM) + r0 + tid] = score_s[tid];
}

// ---------------------------------------------------------------------------
// Kernel 3: softmax over T per batch (sums the OCG partials deterministically).
// ---------------------------------------------------------------------------
__global__ void softmax_kernel(float* __restrict__ d_out) {
    __shared__ float red[1024];
    const int b = blockIdx.x;
    const int tid = threadIdx.x;
    const int i0 = b * T_DIM + tid;
    const int i1 = b * T_DIM + 1024 + tid;
    float s0 = 0.f, s1 = 0.f;
    #pragma unroll
    for (int g = 0; g < OCG; ++g) {
        s0 += g_score_part[g * (B_DIM * T_DIM) + i0];
        s1 += g_score_part[g * (B_DIM * T_DIM) + i1];
    }
    red[tid] = fmaxf(s0, s1);
    __syncthreads();
    for (int s = 512; s > 0; s >>= 1) {
        if (tid < s) red[tid] = fmaxf(red[tid], red[tid + s]);
        __syncthreads();
    }
    const float mx = red[0];
    __syncthreads();
    const float e0 = expf(s0 - mx), e1 = expf(s1 - mx);
    red[tid] = e0 + e1;
    __syncthreads();
    for (int s = 512; s > 0; s >>= 1) {
        if (tid < s) red[tid] += red[tid + s];
        __syncthreads();
    }
    const float inv = 1.f / red[0];
    float* w = d_out + B_DIM * H_DIM + b * T_DIM;
    w[tid] = e0 * inv;
    w[tid + 1024] = e1 * inv;
}

// ---------------------------------------------------------------------------
// Kernel 4a: context partials over T chunks; 4b: deterministic reduce.
// ---------------------------------------------------------------------------
__global__ void __launch_bounds__(1024) ctx_partial_kernel(
    const float* __restrict__ values, const float* __restrict__ d_out_w) {
    __shared__ float w_s[256];
    const int ts = blockIdx.x, b = blockIdx.y;
    const int h = threadIdx.x;
    const float* w = d_out_w + b * T_DIM + ts * 256;
    if (h < 256) w_s[h] = w[h];
    __syncthreads();
    const float* vp = values + ((size_t)b * T_DIM + ts * 256) * H_DIM + h;
    float a0 = 0.f, a1 = 0.f, a2 = 0.f, a3 = 0.f;
    #pragma unroll 8
    for (int t = 0; t < 256; t += 4) {
        a0 += w_s[t + 0] * vp[(size_t)(t + 0) * H_DIM];
        a1 += w_s[t + 1] * vp[(size_t)(t + 1) * H_DIM];
        a2 += w_s[t + 2] * vp[(size_t)(t + 2) * H_DIM];
        a3 += w_s[t + 3] * vp[(size_t)(t + 3) * H_DIM];
    }
    g_ctx_part[(b * 8 + ts) * H_DIM + h] = (a0 + a1) + (a2 + a3);
}

__global__ void __launch_bounds__(1024) ctx_reduce_kernel(float* __restrict__ d_out) {
    const int b = blockIdx.x, h = threadIdx.x;
    float s = 0.f;
    #pragma unroll
    for (int ts = 0; ts < 8; ++ts) s += g_ctx_part[(b * 8 + ts) * H_DIM + h];
    d_out[b * H_DIM + h] = s;
}

// ---------------------------------------------------------------------------
extern "C" void kernel_launch(void* const* d_in, const int* in_sizes, int n_in,
                              void* d_out, int out_size) {
    const float* query  = (const float*)d_in[0];
    const float* values = (const float*)d_in[1];
    const float* Wq     = (const float*)d_in[2];
    const float* bq     = (const float*)d_in[3];
    const float* Wv     = (const float*)d_in[4];
    const float* bv     = (const float*)d_in[5];
    const float* Vw     = (const float*)d_in[6];
    float* out = (float*)d_out;

    cudaFuncSetAttribute(score_kernel, cudaFuncAttributeMaxDynamicSharedMemorySize,
                         SMEM_BYTES);

    __half* vals_h;
    cudaGetSymbolAddress((void**)&vals_h, g_vals_h);
    __half* wv_h;
    cudaGetSymbolAddress((void**)&wv_h, g_wv_h);

    convert_kernel<<<8192, 256>>>(values, vals_h, (B_DIM * T_DIM * (H_DIM / 4)));
    convert_kernel<<<2048, 256>>>(Wv, wv_h, (H_DIM * H_DIM) / 4);
    qproj_kernel<<<dim3(8, B_DIM), 256>>>(query, Wq, bq);
    score_kernel<<<dim3((B_DIM * T_DIM) / 128, OCG), 256, SMEM_BYTES>>>(bv, Vw);
    softmax_kernel<<<B_DIM, 1024>>>(out);
    ctx_partial_kernel<<<dim3(8, B_DIM), 1024>>>(values, out + B_DIM * H_DIM);
    ctx_reduce_kernel<<<B_DIM, 1024>>>(out);
}

// round 13
// speedup vs baseline: 1.2409x; 1.2409x over previous
#include <cuda_runtime.h>
#include <cuda_fp16.h>
#include <math.h>
#include <stdint.h>

#define B_DIM 32
#define T_DIM 2048
#define H_DIM 1024
#define OCG   4                                 // oc groups (CTAs per row-block)

// ---------------------------------------------------------------------------
// Scratch (allocation-free rule: __device__ globals)
// ---------------------------------------------------------------------------
__device__ float  g_qproj[B_DIM * H_DIM];
__device__ float  g_score_part[OCG * B_DIM * T_DIM];
__device__ float  g_ctx_part[B_DIM * 8 * H_DIM];
__device__ __half g_vals_h[(size_t)B_DIM * T_DIM * H_DIM];   // 128 MB
__device__ __half g_wv_h[H_DIM * H_DIM];

// ---------------------------------------------------------------------------
// PTX helpers (sm_80-compatible; tcgen05 is NOT available at compute_103)
// ---------------------------------------------------------------------------
__device__ __forceinline__ uint32_t smem_u32(const void* p) {
    uint32_t a;
    asm("{ .reg .u64 t; cvta.to.shared.u64 t, %1; cvt.u32.u64 %0, t; }" : "=r"(a) : "l"(p));
    return a;
}
__device__ __forceinline__ void cp_async16(uint32_t dst, const void* src) {
    asm volatile("cp.async.cg.shared.global [%0], [%1], 16;" :: "r"(dst), "l"(src));
}
__device__ __forceinline__ void cp_commit() {
    asm volatile("cp.async.commit_group;" ::: "memory");
}
template <int N>
__device__ __forceinline__ void cp_wait() {
    asm volatile("cp.async.wait_group %0;" :: "n"(N) : "memory");
}
__device__ __forceinline__ void ldsm_x4(uint32_t r[4], uint32_t addr) {
    asm volatile("ldmatrix.sync.aligned.m8n8.x4.shared.b16 {%0,%1,%2,%3}, [%4];"
                 : "=r"(r[0]), "=r"(r[1]), "=r"(r[2]), "=r"(r[3]) : "r"(addr));
}
__device__ __forceinline__ void mma_f16(float c[4], const uint32_t a[4], const uint32_t b[2]) {
    asm volatile(
        "mma.sync.aligned.m16n8k16.row.col.f32.f16.f16.f32 "
        "{%0,%1,%2,%3}, {%4,%5,%6,%7}, {%8,%9}, {%0,%1,%2,%3};"
        : "+f"(c[0]), "+f"(c[1]), "+f"(c[2]), "+f"(c[3])
        : "r"(a[0]), "r"(a[1]), "r"(a[2]), "r"(a[3]), "r"(b[0]), "r"(b[1]));
}
__device__ __forceinline__ float fast_tanh(float x) {
    float e = __expf(2.0f * x);
    return 1.0f - 2.0f / (e + 1.0f);
}

// ---------------------------------------------------------------------------
// Kernel 0: fp32 -> fp16 conversion (grid-stride over float4)
// ---------------------------------------------------------------------------
__global__ void convert_kernel(const float* __restrict__ src, __half* __restrict__ dst,
                               int n4) {
    int i = blockIdx.x * blockDim.x + threadIdx.x;
    const int stride = gridDim.x * blockDim.x;
    for (; i < n4; i += stride) {
        float4 v = ((const float4*)src)[i];
        __half2 h0 = __floats2half2_rn(v.x, v.y);
        __half2 h1 = __floats2half2_rn(v.z, v.w);
        ((__half2*)dst)[2 * i + 0] = h0;
        ((__half2*)dst)[2 * i + 1] = h1;
    }
}

// ---------------------------------------------------------------------------
// Kernel 1: q_proj, grid (8 oc, 32 b): warp per output, 16 outputs per warp.
// ---------------------------------------------------------------------------
__global__ void qproj_kernel(const float* __restrict__ query,
                             const float* __restrict__ Wq,
                             const float* __restrict__ bq) {
    __shared__ float q_s[H_DIM];
    const int b = blockIdx.y;
    const int ob = blockIdx.x * 128;
    const int tid = threadIdx.x;
    for (int i = tid; i < H_DIM; i += 256) q_s[i] = query[b * H_DIM + i];
    __syncthreads();
    const int warp = tid >> 5, lane = tid & 31;
    for (int oi = 0; oi < 16; ++oi) {
        const int o = ob + warp * 16 + oi;
        const float* wrow = Wq + (size_t)o * H_DIM;
        float s = 0.f;
        #pragma unroll 8
        for (int h = lane; h < H_DIM; h += 32) s += q_s[h] * wrow[h];
        #pragma unroll
        for (int m = 16; m > 0; m >>= 1) s += __shfl_xor_sync(0xffffffffu, s, m);
        if (lane == 0) g_qproj[b * H_DIM + o] = s + bq[o];
    }
}

// ---------------------------------------------------------------------------
// Kernel 2: fused score GEMM (R11 shape), fp16 m16n8k16 mma.sync + ldmatrix.
// Grid (512 row-blocks, OCG oc-groups), OC_PER=2 passes of 128x128.
// 3-stage cp.async, BK=64. Loads issued AFTER the compute steps each kt so the
// post-barrier issue window feeds the tensor pipe (slack >= 1.5 kt covers DRAM).
// 256 threads = 8 warps (4m x 2n), warp tile 32x64, fp32 accum.
// ---------------------------------------------------------------------------
#define BK       64
#define STAGES   3
#define NKT      (H_DIM / BK)                  // 16
#define LDPH     72                            // padded row stride (halves), 144B
#define ST_H     (128 * LDPH)                  // halves per tile (A or B)
#define OFF_AH   0
#define OFF_BH   (STAGES * ST_H)
#define HALVES   (2 * STAGES * ST_H)
#define OFF_QB   (HALVES / 2)                  // float index
#define OFF_VW   (OFF_QB + 128)
#define OFF_SC   (OFF_VW + 128)
#define SMEM_FLT (OFF_SC + 128)
#define SMEM_BYTES (SMEM_FLT * 4)              // 112128 B
#define OC_PER   (8 / OCG)                     // passes per CTA

__global__ void __launch_bounds__(256, 2) score_kernel(
    const float* __restrict__ bv,
    const float* __restrict__ Vw) {

    extern __shared__ __align__(16) float smem[];
    __half* As = (__half*)smem + OFF_AH;      // [STAGES][128][72]
    __half* Bs = (__half*)smem + OFF_BH;
    float* qb_s = smem + OFF_QB;
    float* vw_s = smem + OFF_VW;
    float* score_s = smem + OFF_SC;

    const int tid = threadIdx.x;
    const int wid = tid >> 5, lane = tid & 31;
    const int warp_m = wid >> 1, warp_n = wid & 1;   // 4 x 2
    const int gid = lane >> 2, tig = lane & 3;
    const int l8 = lane & 7, sel = lane >> 3;

    // Per-warp K-step phase rotation (de-lockstep)
    const int ks0 = ((wid & 3) + ((wid >> 2) << 1)) & 3;

    const int r0 = blockIdx.x * 128;
    const int grp = blockIdx.y;                  // oc group
    const int b  = r0 / T_DIM;
    const float* qp = g_qproj + b * H_DIM;

    if (tid < 128) score_s[tid] = 0.f;

    // Loader thread constants
    const int ld_row = tid >> 3;
    const int ld_ch  = tid & 7;
    const uint32_t ld_soff = (uint32_t)(ld_row * LDPH + ld_ch * 8) * 2;  // bytes
    const uint32_t a_sbase = smem_u32(As) + ld_soff;
    const uint32_t b_sbase = smem_u32(Bs) + ld_soff;
    const __half* a_gbase = g_vals_h + (size_t)(r0 + ld_row) * H_DIM + ld_ch * 8;
    const size_t  g_row_step = (size_t)32 * H_DIM;

    // ldmatrix lane addressing (halves)
    const int a_row = warp_m * 32 + ((sel & 1) ? 8 : 0) + l8;
    const int a_kof = (sel & 2) ? 8 : 0;
    const int b_row = warp_n * 64 + ((sel & 2) ? 8 : 0) + l8;
    const int b_kof = (sel & 1) ? 8 : 0;
    const uint32_t a_lbase = smem_u32(As + a_row * LDPH + a_kof);
    const uint32_t b_lbase = smem_u32(Bs + b_row * LDPH + b_kof);
    const uint32_t stg_b = ST_H * 2;

    float sacc[4] = {0.f, 0.f, 0.f, 0.f};

    for (int oc = grp * OC_PER; oc < grp * OC_PER + OC_PER; ++oc) {
        const int ob = oc * 128;
        const __half* b_gbase = g_wv_h + (size_t)(ob + ld_row) * H_DIM + ld_ch * 8;
        __syncthreads();                 // prev pass fully done (epilogue + slots)
        if (tid < 128) {
            qb_s[tid] = qp[ob + tid] + bv[ob + tid];
            vw_s[tid] = Vw[ob + tid];
        }

        float c[2][8][4];
        #pragma unroll
        for (int mt = 0; mt < 2; ++mt)
            #pragma unroll
            for (int nt = 0; nt < 8; ++nt)
                #pragma unroll
                for (int i = 0; i < 4; ++i) c[mt][nt][i] = 0.f;

        // prologue: fill stages 0,1
        #pragma unroll
        for (int s = 0; s < STAGES - 1; ++s) {
            #pragma unroll
            for (int it = 0; it < 4; ++it) {
                cp_async16(a_sbase + s * stg_b + it * (32 * LDPH * 2),
                           a_gbase + s * BK + it * g_row_step);
                cp_async16(b_sbase + s * stg_b + it * (32 * LDPH * 2),
                           b_gbase + s * BK + it * g_row_step);
            }
            cp_commit();
        }

        int cur = 0, nxt = STAGES - 1;
        for (int kt = 0; kt < NKT; ++kt) {
            cp_wait<STAGES - 2>();       // stage `cur` complete
            __syncthreads();             // slot `nxt` free (consumed at kt-1)

            const uint32_t a_base = a_lbase + cur * stg_b;
            const uint32_t b_base = b_lbase + cur * stg_b;

            // compute FIRST: keep the tensor pipe fed right after the barrier
            #pragma unroll
            for (int kss = 0; kss < 4; ++kss) {
                const int ks = (kss + ks0) & 3;
                const uint32_t koff = (uint32_t)ks * 32;
                uint32_t af[2][4], bf[8][2];
                #pragma unroll
                for (int mt = 0; mt < 2; ++mt)
                    ldsm_x4(af[mt], a_base + mt * (16 * LDPH * 2) + koff);
                #pragma unroll
                for (int np = 0; np < 4; ++np) {
                    uint32_t r[4];
                    ldsm_x4(r, b_base + np * (16 * LDPH * 2) + koff);
                    bf[np * 2 + 0][0] = r[0];
                    bf[np * 2 + 0][1] = r[1];
                    bf[np * 2 + 1][0] = r[2];
                    bf[np * 2 + 1][1] = r[3];
                }
                #pragma unroll
                for (int mt = 0; mt < 2; ++mt)
                    #pragma unroll
                    for (int nt = 0; nt < 8; ++nt)
                        mma_f16(c[mt][nt], af[mt], bf[nt]);
            }

            // loads LAST: slack (>=1.5 kt) still covers DRAM latency
            const int nk = kt + STAGES - 1;
            if (nk < NKT) {
                #pragma unroll
                for (int it = 0; it < 4; ++it) {
                    cp_async16(a_sbase + nxt * stg_b + it * (32 * LDPH * 2),
                               a_gbase + nk * BK + it * g_row_step);
                    cp_async16(b_sbase + nxt * stg_b + it * (32 * LDPH * 2),
                               b_gbase + nk * BK + it * g_row_step);
                }
            }
            cp_commit();

            cur = (cur == STAGES - 1) ? 0 : cur + 1;
            nxt = (nxt == STAGES - 1) ? 0 : nxt + 1;
        }

        // Epilogue: tanh + Vw contraction into per-lane row partials
        #pragma unroll
        for (int nt = 0; nt < 8; ++nt) {
            const int col0 = warp_n * 64 + nt * 8 + 2 * tig;
            const float vw0 = vw_s[col0],     qb0 = qb_s[col0];
            const float vw1 = vw_s[col0 + 1], qb1 = qb_s[col0 + 1];
            #pragma unroll
            for (int mt = 0; mt < 2; ++mt) {
                sacc[mt * 2 + 0] += vw0 * fast_tanh(c[mt][nt][0] + qb0)
                                  + vw1 * fast_tanh(c[mt][nt][1] + qb1);
                sacc[mt * 2 + 1] += vw0 * fast_tanh(c[mt][nt][2] + qb0)
                                  + vw1 * fast_tanh(c[mt][nt][3] + qb1);
            }
        }
    }

    #pragma unroll
    for (int i = 0; i < 4; ++i) {
        sacc[i] += __shfl_xor_sync(0xffffffffu, sacc[i], 1);
        sacc[i] += __shfl_xor_sync(0xffffffffu, sacc[i], 2);
    }
    if (tig == 0) {
        #pragma unroll
        for (int i = 0; i < 4; ++i) {
            const int row = warp_m * 32 + (i >> 1) * 16 + gid + (i & 1) * 8;
            atomicAdd(&score_s[row], sacc[i]);
        }
    }
    __syncthreads();
    if (tid < 128) g_score_part[grp * (B_DIM * T_DIM) + r0 + tid] = score_s[tid];
}

// ---------------------------------------------------------------------------
// Kernel 3: softmax over T per batch (sums the OCG partials deterministically).
// ---------------------------------------------------------------------------
__global__ void softmax_kernel(float* __restrict__ d_out) {
    __shared__ float red[1024];
    const int b = blockIdx.x;
    const int tid = threadIdx.x;
    const int i0 = b * T_DIM + tid;
    const int i1 = b * T_DIM + 1024 + tid;
    float s0 = 0.f, s1 = 0.f;
    #pragma unroll
    for (int g = 0; g < OCG; ++g) {
        s0 += g_score_part[g * (B_DIM * T_DIM) + i0];
        s1 += g_score_part[g * (B_DIM * T_DIM) + i1];
    }
    red[tid] = fmaxf(s0, s1);
    __syncthreads();
    for (int s = 512; s > 0; s >>= 1) {
        if (tid < s) red[tid] = fmaxf(red[tid], red[tid + s]);
        __syncthreads();
    }
    const float mx = red[0];
    __syncthreads();
    const float e0 = expf(s0 - mx), e1 = expf(s1 - mx);
    red[tid] = e0 + e1;
    __syncthreads();
    for (int s = 512; s > 0; s >>= 1) {
        if (tid < s) red[tid] += red[tid + s];
        __syncthreads();
    }
    const float inv = 1.f / red[0];
    float* w = d_out + B_DIM * H_DIM + b * T_DIM;
    w[tid] = e0 * inv;
    w[tid + 1024] = e1 * inv;
}

// ---------------------------------------------------------------------------
// Kernel 4a: context partials over T chunks (reads fp16 values: half traffic);
// 4b: deterministic reduce.
// ---------------------------------------------------------------------------
__global__ void __launch_bounds__(1024) ctx_partial_kernel(
    const float* __restrict__ d_out_w) {
    __shared__ float w_s[256];
    const int ts = blockIdx.x, b = blockIdx.y;
    const int h = threadIdx.x;
    const float* w = d_out_w + b * T_DIM + ts * 256;
    if (h < 256) w_s[h] = w[h];
    __syncthreads();
    const __half* vp = g_vals_h + ((size_t)b * T_DIM + ts * 256) * H_DIM + h;
    float a0 = 0.f, a1 = 0.f, a2 = 0.f, a3 = 0.f;
    #pragma unroll 8
    for (int t = 0; t < 256; t += 4) {
        a0 += w_s[t + 0] * __half2float(vp[(size_t)(t + 0) * H_DIM]);
        a1 += w_s[t + 1] * __half2float(vp[(size_t)(t + 1) * H_DIM]);
        a2 += w_s[t + 2] * __half2float(vp[(size_t)(t + 2) * H_DIM]);
        a3 += w_s[t + 3] * __half2float(vp[(size_t)(t + 3) * H_DIM]);
    }
    g_ctx_part[(b * 8 + ts) * H_DIM + h] = (a0 + a1) + (a2 + a3);
}

__global__ void __launch_bounds__(1024) ctx_reduce_kernel(float* __restrict__ d_out) {
    const int b = blockIdx.x, h = threadIdx.x;
    float s = 0.f;
    #pragma unroll
    for (int ts = 0; ts < 8; ++ts) s += g_ctx_part[(b * 8 + ts) * H_DIM + h];
    d_out[b * H_DIM + h] = s;
}

// ---------------------------------------------------------------------------
extern "C" void kernel_launch(void* const* d_in, const int* in_sizes, int n_in,
                              void* d_out, int out_size) {
    const float* query  = (const float*)d_in[0];
    const float* values = (const float*)d_in[1];
    const float* Wq     = (const float*)d_in[2];
    const float* bq     = (const float*)d_in[3];
    const float* Wv     = (const float*)d_in[4];
    const float* bv     = (const float*)d_in[5];
    const float* Vw     = (const float*)d_in[6];
    float* out = (float*)d_out;

    cudaFuncSetAttribute(score_kernel, cudaFuncAttributeMaxDynamicSharedMemorySize,
                         SMEM_BYTES);

    __half* vals_h;
    cudaGetSymbolAddress((void**)&vals_h, g_vals_h);
    __half* wv_h;
    cudaGetSymbolAddress((void**)&wv_h, g_wv_h);

    convert_kernel<<<8192, 256>>>(values, vals_h, (B_DIM * T_DIM * (H_DIM / 4)));
    convert_kernel<<<2048, 256>>>(Wv, wv_h, (H_DIM * H_DIM) / 4);
    qproj_kernel<<<dim3(8, B_DIM), 256>>>(query, Wq, bq);
    score_kernel<<<dim3((B_DIM * T_DIM) / 128, OCG), 256, SMEM_BYTES>>>(bv, Vw);
    softmax_kernel<<<B_DIM, 1024>>>(out);
    ctx_partial_kernel<<<dim3(8, B_DIM), 1024>>>(out + B_DIM * H_DIM);
    ctx_reduce_kernel<<<B_DIM, 1024>>>(out);
}

// round 14
// speedup vs baseline: 1.2467x; 1.0046x over previous
#include <cuda_runtime.h>
#include <cuda_fp16.h>
#include <math.h>
#include <stdint.h>

#define B_DIM 32
#define T_DIM 2048
#define H_DIM 1024
#define OCG   4                                 // oc groups (CTAs per row-block)

// ---------------------------------------------------------------------------
// Scratch (allocation-free rule: __device__ globals)
// ---------------------------------------------------------------------------
__device__ float  g_qproj[B_DIM * H_DIM];
__device__ float  g_score_part[OCG * B_DIM * T_DIM];
__device__ float  g_ctx_part[B_DIM * 8 * H_DIM];
__device__ __half g_vals_h[(size_t)B_DIM * T_DIM * H_DIM];   // 128 MB
__device__ __half g_wv_h[H_DIM * H_DIM];

// ---------------------------------------------------------------------------
// PTX helpers (sm_80-compatible; tcgen05 is NOT available at compute_103)
// ---------------------------------------------------------------------------
__device__ __forceinline__ uint32_t smem_u32(const void* p) {
    uint32_t a;
    asm("{ .reg .u64 t; cvta.to.shared.u64 t, %1; cvt.u32.u64 %0, t; }" : "=r"(a) : "l"(p));
    return a;
}
__device__ __forceinline__ void cp_async16(uint32_t dst, const void* src) {
    asm volatile("cp.async.cg.shared.global [%0], [%1], 16;" :: "r"(dst), "l"(src));
}
__device__ __forceinline__ void cp_commit() {
    asm volatile("cp.async.commit_group;" ::: "memory");
}
template <int N>
__device__ __forceinline__ void cp_wait() {
    asm volatile("cp.async.wait_group %0;" :: "n"(N) : "memory");
}
__device__ __forceinline__ void ldsm_x4(uint32_t r[4], uint32_t addr) {
    asm volatile("ldmatrix.sync.aligned.m8n8.x4.shared.b16 {%0,%1,%2,%3}, [%4];"
                 : "=r"(r[0]), "=r"(r[1]), "=r"(r[2]), "=r"(r[3]) : "r"(addr));
}
__device__ __forceinline__ void mma_f16(float c[4], const uint32_t a[4], const uint32_t b[2]) {
    asm volatile(
        "mma.sync.aligned.m16n8k16.row.col.f32.f16.f16.f32 "
        "{%0,%1,%2,%3}, {%4,%5,%6,%7}, {%8,%9}, {%0,%1,%2,%3};"
        : "+f"(c[0]), "+f"(c[1]), "+f"(c[2]), "+f"(c[3])
        : "r"(a[0]), "r"(a[1]), "r"(a[2]), "r"(a[3]), "r"(b[0]), "r"(b[1]));
}
__device__ __forceinline__ float fast_tanh(float x) {
    float e = __expf(2.0f * x);
    return 1.0f - 2.0f / (e + 1.0f);
}

// ---------------------------------------------------------------------------
// Kernel 0: fp32 -> fp16 conversion (grid-stride over float4)
// ---------------------------------------------------------------------------
__global__ void convert_kernel(const float* __restrict__ src, __half* __restrict__ dst,
                               int n4) {
    int i = blockIdx.x * blockDim.x + threadIdx.x;
    const int stride = gridDim.x * blockDim.x;
    for (; i < n4; i += stride) {
        float4 v = ((const float4*)src)[i];
        __half2 h0 = __floats2half2_rn(v.x, v.y);
        __half2 h1 = __floats2half2_rn(v.z, v.w);
        ((__half2*)dst)[2 * i + 0] = h0;
        ((__half2*)dst)[2 * i + 1] = h1;
    }
}

// ---------------------------------------------------------------------------
// Kernel 1: q_proj, grid (8 oc, 32 b): warp per output, 16 outputs per warp.
// ---------------------------------------------------------------------------
__global__ void qproj_kernel(const float* __restrict__ query,
                             const float* __restrict__ Wq,
                             const float* __restrict__ bq) {
    __shared__ float q_s[H_DIM];
    const int b = blockIdx.y;
    const int ob = blockIdx.x * 128;
    const int tid = threadIdx.x;
    for (int i = tid; i < H_DIM; i += 256) q_s[i] = query[b * H_DIM + i];
    __syncthreads();
    const int warp = tid >> 5, lane = tid & 31;
    for (int oi = 0; oi < 16; ++oi) {
        const int o = ob + warp * 16 + oi;
        const float* wrow = Wq + (size_t)o * H_DIM;
        float s = 0.f;
        #pragma unroll 8
        for (int h = lane; h < H_DIM; h += 32) s += q_s[h] * wrow[h];
        #pragma unroll
        for (int m = 16; m > 0; m >>= 1) s += __shfl_xor_sync(0xffffffffu, s, m);
        if (lane == 0) g_qproj[b * H_DIM + o] = s + bq[o];
    }
}

// ---------------------------------------------------------------------------
// Kernel 2: fused score GEMM (R11 shape), fp16 m16n8k16 mma.sync + ldmatrix.
// Grid (512 row-blocks, OCG oc-groups), OC_PER=2 passes of 128x128.
// 3-stage cp.async, BK=64. Loads issued AFTER the compute steps each kt so the
// post-barrier issue window feeds the tensor pipe (slack >= 1.5 kt covers DRAM).
// 256 threads = 8 warps (4m x 2n), warp tile 32x64, fp32 accum.
// ---------------------------------------------------------------------------
#define BK       64
#define STAGES   3
#define NKT      (H_DIM / BK)                  // 16
#define LDPH     72                            // padded row stride (halves), 144B
#define ST_H     (128 * LDPH)                  // halves per tile (A or B)
#define OFF_AH   0
#define OFF_BH   (STAGES * ST_H)
#define HALVES   (2 * STAGES * ST_H)
#define OFF_QB   (HALVES / 2)                  // float index
#define OFF_VW   (OFF_QB + 128)
#define OFF_SC   (OFF_VW + 128)
#define SMEM_FLT (OFF_SC + 128)
#define SMEM_BYTES (SMEM_FLT * 4)              // 112128 B
#define OC_PER   (8 / OCG)                     // passes per CTA

__global__ void __launch_bounds__(256, 2) score_kernel(
    const float* __restrict__ bv,
    const float* __restrict__ Vw) {

    extern __shared__ __align__(16) float smem[];
    __half* As = (__half*)smem + OFF_AH;      // [STAGES][128][72]
    __half* Bs = (__half*)smem + OFF_BH;
    float* qb_s = smem + OFF_QB;
    float* vw_s = smem + OFF_VW;
    float* score_s = smem + OFF_SC;

    const int tid = threadIdx.x;
    const int wid = tid >> 5, lane = tid & 31;
    const int warp_m = wid >> 1, warp_n = wid & 1;   // 4 x 2
    const int gid = lane >> 2, tig = lane & 3;
    const int l8 = lane & 7, sel = lane >> 3;

    // Per-warp K-step phase rotation (de-lockstep)
    const int ks0 = ((wid & 3) + ((wid >> 2) << 1)) & 3;

    const int r0 = blockIdx.x * 128;
    const int grp = blockIdx.y;                  // oc group
    const int b  = r0 / T_DIM;
    const float* qp = g_qproj + b * H_DIM;

    if (tid < 128) score_s[tid] = 0.f;

    // Loader thread constants
    const int ld_row = tid >> 3;
    const int ld_ch  = tid & 7;
    const uint32_t ld_soff = (uint32_t)(ld_row * LDPH + ld_ch * 8) * 2;  // bytes
    const uint32_t a_sbase = smem_u32(As) + ld_soff;
    const uint32_t b_sbase = smem_u32(Bs) + ld_soff;
    const __half* a_gbase = g_vals_h + (size_t)(r0 + ld_row) * H_DIM + ld_ch * 8;
    const size_t  g_row_step = (size_t)32 * H_DIM;

    // ldmatrix lane addressing (halves)
    const int a_row = warp_m * 32 + ((sel & 1) ? 8 : 0) + l8;
    const int a_kof = (sel & 2) ? 8 : 0;
    const int b_row = warp_n * 64 + ((sel & 2) ? 8 : 0) + l8;
    const int b_kof = (sel & 1) ? 8 : 0;
    const uint32_t a_lbase = smem_u32(As + a_row * LDPH + a_kof);
    const uint32_t b_lbase = smem_u32(Bs + b_row * LDPH + b_kof);
    const uint32_t stg_b = ST_H * 2;

    float sacc[4] = {0.f, 0.f, 0.f, 0.f};

    for (int oc = grp * OC_PER; oc < grp * OC_PER + OC_PER; ++oc) {
        const int ob = oc * 128;
        const __half* b_gbase = g_wv_h + (size_t)(ob + ld_row) * H_DIM + ld_ch * 8;
        __syncthreads();                 // prev pass fully done (epilogue + slots)
        if (tid < 128) {
            qb_s[tid] = qp[ob + tid] + bv[ob + tid];
            vw_s[tid] = Vw[ob + tid];
        }

        float c[2][8][4];
        #pragma unroll
        for (int mt = 0; mt < 2; ++mt)
            #pragma unroll
            for (int nt = 0; nt < 8; ++nt)
                #pragma unroll
                for (int i = 0; i < 4; ++i) c[mt][nt][i] = 0.f;

        // prologue: fill stages 0,1
        #pragma unroll
        for (int s = 0; s < STAGES - 1; ++s) {
            #pragma unroll
            for (int it = 0; it < 4; ++it) {
                cp_async16(a_sbase + s * stg_b + it * (32 * LDPH * 2),
                           a_gbase + s * BK + it * g_row_step);
                cp_async16(b_sbase + s * stg_b + it * (32 * LDPH * 2),
                           b_gbase + s * BK + it * g_row_step);
            }
            cp_commit();
        }

        int cur = 0, nxt = STAGES - 1;
        for (int kt = 0; kt < NKT; ++kt) {
            cp_wait<STAGES - 2>();       // stage `cur` complete
            __syncthreads();             // slot `nxt` free (consumed at kt-1)

            const uint32_t a_base = a_lbase + cur * stg_b;
            const uint32_t b_base = b_lbase + cur * stg_b;

            // compute FIRST: keep the tensor pipe fed right after the barrier
            #pragma unroll
            for (int kss = 0; kss < 4; ++kss) {
                const int ks = (kss + ks0) & 3;
                const uint32_t koff = (uint32_t)ks * 32;
                uint32_t af[2][4], bf[8][2];
                #pragma unroll
                for (int mt = 0; mt < 2; ++mt)
                    ldsm_x4(af[mt], a_base + mt * (16 * LDPH * 2) + koff);
                #pragma unroll
                for (int np = 0; np < 4; ++np) {
                    uint32_t r[4];
                    ldsm_x4(r, b_base + np * (16 * LDPH * 2) + koff);
                    bf[np * 2 + 0][0] = r[0];
                    bf[np * 2 + 0][1] = r[1];
                    bf[np * 2 + 1][0] = r[2];
                    bf[np * 2 + 1][1] = r[3];
                }
                #pragma unroll
                for (int mt = 0; mt < 2; ++mt)
                    #pragma unroll
                    for (int nt = 0; nt < 8; ++nt)
                        mma_f16(c[mt][nt], af[mt], bf[nt]);
            }

            // loads LAST: slack (>=1.5 kt) still covers DRAM latency
            const int nk = kt + STAGES - 1;
            if (nk < NKT) {
                #pragma unroll
                for (int it = 0; it < 4; ++it) {
                    cp_async16(a_sbase + nxt * stg_b + it * (32 * LDPH * 2),
                               a_gbase + nk * BK + it * g_row_step);
                    cp_async16(b_sbase + nxt * stg_b + it * (32 * LDPH * 2),
                               b_gbase + nk * BK + it * g_row_step);
                }
            }
            cp_commit();

            cur = (cur == STAGES - 1) ? 0 : cur + 1;
            nxt = (nxt == STAGES - 1) ? 0 : nxt + 1;
        }

        // Epilogue: tanh + Vw contraction into per-lane row partials
        #pragma unroll
        for (int nt = 0; nt < 8; ++nt) {
            const int col0 = warp_n * 64 + nt * 8 + 2 * tig;
            const float vw0 = vw_s[col0],     qb0 = qb_s[col0];
            const float vw1 = vw_s[col0 + 1], qb1 = qb_s[col0 + 1];
            #pragma unroll
            for (int mt = 0; mt < 2; ++mt) {
                sacc[mt * 2 + 0] += vw0 * fast_tanh(c[mt][nt][0] + qb0)
                                  + vw1 * fast_tanh(c[mt][nt][1] + qb1);
                sacc[mt * 2 + 1] += vw0 * fast_tanh(c[mt][nt][2] + qb0)
                                  + vw1 * fast_tanh(c[mt][nt][3] + qb1);
            }
        }
    }

    #pragma unroll
    for (int i = 0; i < 4; ++i) {
        sacc[i] += __shfl_xor_sync(0xffffffffu, sacc[i], 1);
        sacc[i] += __shfl_xor_sync(0xffffffffu, sacc[i], 2);
    }
    if (tig == 0) {
        #pragma unroll
        for (int i = 0; i < 4; ++i) {
            const int row = warp_m * 32 + (i >> 1) * 16 + gid + (i & 1) * 8;
            atomicAdd(&score_s[row], sacc[i]);
        }
    }
    __syncthreads();
    if (tid < 128) g_score_part[grp * (B_DIM * T_DIM) + r0 + tid] = score_s[tid];
}

// ---------------------------------------------------------------------------
// Kernel 3: softmax over T per batch (sums the OCG partials deterministically).
// ---------------------------------------------------------------------------
__global__ void softmax_kernel(float* __restrict__ d_out) {
    __shared__ float red[1024];
    const int b = blockIdx.x;
    const int tid = threadIdx.x;
    const int i0 = b * T_DIM + tid;
    const int i1 = b * T_DIM + 1024 + tid;
    float s0 = 0.f, s1 = 0.f;
    #pragma unroll
    for (int g = 0; g < OCG; ++g) {
        s0 += g_score_part[g * (B_DIM * T_DIM) + i0];
        s1 += g_score_part[g * (B_DIM * T_DIM) + i1];
    }
    red[tid] = fmaxf(s0, s1);
    __syncthreads();
    for (int s = 512; s > 0; s >>= 1) {
        if (tid < s) red[tid] = fmaxf(red[tid], red[tid + s]);
        __syncthreads();
    }
    const float mx = red[0];
    __syncthreads();
    const float e0 = expf(s0 - mx), e1 = expf(s1 - mx);
    red[tid] = e0 + e1;
    __syncthreads();
    for (int s = 512; s > 0; s >>= 1) {
        if (tid < s) red[tid] += red[tid + s];
        __syncthreads();
    }
    const float inv = 1.f / red[0];
    float* w = d_out + B_DIM * H_DIM + b * T_DIM;
    w[tid] = e0 * inv;
    w[tid + 1024] = e1 * inv;
}

// ---------------------------------------------------------------------------
// Kernel 4a: context partials over T chunks (reads fp16 values: half traffic);
// 4b: deterministic reduce.
// ---------------------------------------------------------------------------
__global__ void __launch_bounds__(1024) ctx_partial_kernel(
    const float* __restrict__ d_out_w) {
    __shared__ float w_s[256];
    const int ts = blockIdx.x, b = blockIdx.y;
    const int h = threadIdx.x;
    const float* w = d_out_w + b * T_DIM + ts * 256;
    if (h < 256) w_s[h] = w[h];
    __syncthreads();
    const __half* vp = g_vals_h + ((size_t)b * T_DIM + ts * 256) * H_DIM + h;
    float a0 = 0.f, a1 = 0.f, a2 = 0.f, a3 = 0.f;
    #pragma unroll 8
    for (int t = 0; t < 256; t += 4) {
        a0 += w_s[t + 0] * __half2float(vp[(size_t)(t + 0) * H_DIM]);
        a1 += w_s[t + 1] * __half2float(vp[(size_t)(t + 1) * H_DIM]);
        a2 += w_s[t + 2] * __half2float(vp[(size_t)(t + 2) * H_DIM]);
        a3 += w_s[t + 3] * __half2float(vp[(size_t)(t + 3) * H_DIM]);
    }
    g_ctx_part[(b * 8 + ts) * H_DIM + h] = (a0 + a1) + (a2 + a3);
}

__global__ void __launch_bounds__(1024) ctx_reduce_kernel(float* __restrict__ d_out) {
    const int b = blockIdx.x, h = threadIdx.x;
    float s = 0.f;
    #pragma unroll
    for (int ts = 0; ts < 8; ++ts) s += g_ctx_part[(b * 8 + ts) * H_DIM + h];
    d_out[b * H_DIM + h] = s;
}

// ---------------------------------------------------------------------------
extern "C" void kernel_launch(void* const* d_in, const int* in_sizes, int n_in,
                              void* d_out, int out_size) {
    const float* query  = (const float*)d_in[0];
    const float* values = (const float*)d_in[1];
    const float* Wq     = (const float*)d_in[2];
    const float* bq     = (const float*)d_in[3];
    const float* Wv     = (const float*)d_in[4];
    const float* bv     = (const float*)d_in[5];
    const float* Vw     = (const float*)d_in[6];
    float* out = (float*)d_out;

    cudaFuncSetAttribute(score_kernel, cudaFuncAttributeMaxDynamicSharedMemorySize,
                         SMEM_BYTES);

    __half* vals_h;
    cudaGetSymbolAddress((void**)&vals_h, g_vals_h);
    __half* wv_h;
    cudaGetSymbolAddress((void**)&wv_h, g_wv_h);

    convert_kernel<<<8192, 256>>>(values, vals_h, (B_DIM * T_DIM * (H_DIM / 4)));
    convert_kernel<<<2048, 256>>>(Wv, wv_h, (H_DIM * H_DIM) / 4);
    qproj_kernel<<<dim3(8, B_DIM), 256>>>(query, Wq, bq);
    score_kernel<<<dim3((B_DIM * T_DIM) / 128, OCG), 256, SMEM_BYTES>>>(bv, Vw);
    softmax_kernel<<<B_DIM, 1024>>>(out);
    ctx_partial_kernel<<<dim3(8, B_DIM), 1024>>>(out + B_DIM * H_DIM);
    ctx_reduce_kernel<<<B_DIM, 1024>>>(out);
}